// round 2
// baseline (speedup 1.0000x reference)
#include <cuda_runtime.h>

// Problem constants (fixed by the dataset)
#define L_WIN   10
#define D_EMB   100
#define V_POI   1000
#define V_HOUR  24
#define V_WD    7
#define NCOLS   (V_POI + V_HOUR + V_WD)   // 1031 output columns
#define N_HW    (V_HOUR * V_WD)           // 168 hour*weekday combo rows
#define NROWS   (V_POI + N_HW)            // 1168 token rows (poi | hw-combo)
#define TLSTRIDE 1056                     // padded col stride = 33*128B lines

// Token-logit table:
//  rows [0,1000):     TL[p, n]      = emb_poi[p]  . W(n)[0:100]
//  rows [1000,1168):  TL[1000+h*7+w, n] = emb_hour[h] . W(n)[100:200]
//                                       + emb_wd[w]  . W(n)[200:300]
//  cols [0,1000)=poi logits, [1000,1024)=hour, [1024,1031)=weekday, rest 0-pad.
__device__ __align__(128) float g_TL[NROWS * TLSTRIDE];   // 4.93 MB scratch

// ---------------------------------------------------------------------------
// Kernel 1: build the token-logit table (incl. folded hour*wd combo rows).
// Tile: 8 rows x 32 cols. Each row uses two 100-wide contraction segments.
// ---------------------------------------------------------------------------
__global__ void build_tl_kernel(const float* __restrict__ emb_poi,
                                const float* __restrict__ emb_hour,
                                const float* __restrict__ emb_wd,
                                const float* __restrict__ W_poi,
                                const float* __restrict__ W_hour,
                                const float* __restrict__ W_wd) {
    __shared__ float Ws[32][301];   // stride 301: gcd(301%32,32)=1 -> conflict-free
    __shared__ float Es[8][200];    // per-row: [0:100)=segA emb, [100:200)=segB emb

    const int n0  = blockIdx.x * 32;
    const int r0  = blockIdx.y * 8;
    const int tid = threadIdx.y * 32 + threadIdx.x;   // 256 threads

    // W rows (300-wide) for the 32 output columns of this tile
    for (int idx = tid; idx < 32 * 300; idx += 256) {
        int j = idx / 300, d = idx - j * 300;
        int n = n0 + j;
        float v = 0.f;
        if (n < V_POI)                  v = W_poi[n * 300 + d];
        else if (n < V_POI + V_HOUR)    v = W_hour[(n - V_POI) * 300 + d];
        else if (n < NCOLS)             v = W_wd[(n - V_POI - V_HOUR) * 300 + d];
        Ws[j][d] = v;
    }
    // Effective embeddings (two 100-wide segments) for the 8 rows of this tile
    for (int idx = tid; idx < 8 * 200; idx += 256) {
        int i = idx / 200, d = idx - i * 200;
        int r = r0 + i;
        float v = 0.f;
        if (r < V_POI) {
            if (d < 100) v = emb_poi[r * D_EMB + d];          // segB stays 0
        } else if (r < NROWS) {
            int c = r - V_POI, h = c / V_WD, w = c - h * V_WD;
            v = (d < 100) ? emb_hour[h * D_EMB + d]
                          : emb_wd[w * D_EMB + (d - 100)];
        }
        Es[i][d] = v;
    }
    __syncthreads();

    const int i = threadIdx.y;
    const int j = threadIdx.x;
    const int r = r0 + i;
    if (r >= NROWS) return;

    // segment offsets into the 300-wide W row
    const int aoff0 = (r < V_POI) ? 0   : 100;
    const int aoff1 = (r < V_POI) ? 100 : 200;   // segB is zero for poi rows

    float acc = 0.f;
#pragma unroll
    for (int d = 0; d < D_EMB; d++) {
        acc += Es[i][d]       * Ws[j][aoff0 + d];
        acc += Es[i][100 + d] * Ws[j][aoff1 + d];
    }
    // cols >= NCOLS have zero W rows -> pad columns are written as 0
    g_TL[r * TLSTRIDE + n0 + j] = acc;
}

// ---------------------------------------------------------------------------
// Kernel 2: per-batch gather-sum: 2 rows per valid position (poi + hw-combo).
// One block per batch element, 256 threads:
//   group A: cols [4*tid, 4*tid+4)          covers 0..1023
//   group B: cols [1024+4*tid, ...) tid<8   covers 1024..1055
// ---------------------------------------------------------------------------
__device__ __forceinline__ void emit_col(float* __restrict__ out, int B, int b, int n,
                                         float sum, float inv,
                                         const float* __restrict__ b_poi,
                                         const float* __restrict__ b_hour,
                                         const float* __restrict__ b_wd) {
    if (n < V_POI) {
        out[(size_t)b * V_POI + n] = sum * inv + b_poi[n];
    } else if (n < V_POI + V_HOUR) {
        out[(size_t)B * V_POI + (size_t)b * V_HOUR + (n - V_POI)] =
            sum * inv + b_hour[n - V_POI];
    } else if (n < NCOLS) {
        out[(size_t)B * (V_POI + V_HOUR) + (size_t)b * V_WD + (n - V_POI - V_HOUR)] =
            sum * inv + b_wd[n - V_POI - V_HOUR];
    }
}

__global__ void cbow_gather_kernel(const int* __restrict__ x,
                                   const int* __restrict__ lens,
                                   const float* __restrict__ b_poi,
                                   const float* __restrict__ b_hour,
                                   const float* __restrict__ b_wd,
                                   float* __restrict__ out,
                                   int B) {
    __shared__ int   s_off[2 * L_WIN];   // row offsets in float4 units
    __shared__ int   s_T;
    __shared__ float s_inv;

    const int b   = blockIdx.x;
    const int tid = threadIdx.x;

    if (tid < 2 * L_WIN) {
        int l = tid >> 1;
        const int* xp = x + (b * L_WIN + l) * 3;
        int row;
        if ((tid & 1) == 0) row = xp[0];                          // poi token
        else                row = V_POI + xp[1] * V_WD + xp[2];   // hw combo
        s_off[tid] = row * (TLSTRIDE / 4);
    }
    if (tid == 0) {
        int e = lens[b];
        e = min(max(e, 1), L_WIN);
        s_T   = e * 2;                 // first 2e entries = positions l < e
        s_inv = 1.0f / (float)e;
    }
    __syncthreads();

    const int   T   = s_T;
    const float inv = s_inv;

    float4 a0 = make_float4(0.f, 0.f, 0.f, 0.f);
    float4 c0 = make_float4(0.f, 0.f, 0.f, 0.f);   // second acc for ILP
    float4 a1 = make_float4(0.f, 0.f, 0.f, 0.f);
    const bool two = (tid < 8);   // cols 1024..1055 (warp 0 only)

    const float4* __restrict__ TL4 = reinterpret_cast<const float4*>(g_TL);

    int t = 0;
    for (; t + 2 <= T; t += 2) {     // unroll x2: batch LDGs, 2 accumulators
        const float4* r0 = TL4 + s_off[t];
        const float4* r1 = TL4 + s_off[t + 1];
        float4 v = r0[tid];
        float4 u = r1[tid];
        a0.x += v.x; a0.y += v.y; a0.z += v.z; a0.w += v.w;
        c0.x += u.x; c0.y += u.y; c0.z += u.z; c0.w += u.w;
        if (two) {
            float4 w0 = r0[256 + tid];
            float4 w1 = r1[256 + tid];
            a1.x += w0.x + w1.x; a1.y += w0.y + w1.y;
            a1.z += w0.z + w1.z; a1.w += w0.w + w1.w;
        }
    }
    if (t < T) {                     // T is even (2e) — kept for safety
        const float4* r0 = TL4 + s_off[t];
        float4 v = r0[tid];
        a0.x += v.x; a0.y += v.y; a0.z += v.z; a0.w += v.w;
        if (two) {
            float4 w0 = r0[256 + tid];
            a1.x += w0.x; a1.y += w0.y; a1.z += w0.z; a1.w += w0.w;
        }
    }
    a0.x += c0.x; a0.y += c0.y; a0.z += c0.z; a0.w += c0.w;

    const int n0 = tid * 4;
    emit_col(out, B, b, n0 + 0, a0.x, inv, b_poi, b_hour, b_wd);
    emit_col(out, B, b, n0 + 1, a0.y, inv, b_poi, b_hour, b_wd);
    emit_col(out, B, b, n0 + 2, a0.z, inv, b_poi, b_hour, b_wd);
    emit_col(out, B, b, n0 + 3, a0.w, inv, b_poi, b_hour, b_wd);
    if (two) {
        const int n1 = 1024 + tid * 4;
        emit_col(out, B, b, n1 + 0, a1.x, inv, b_poi, b_hour, b_wd);
        emit_col(out, B, b, n1 + 1, a1.y, inv, b_poi, b_hour, b_wd);
        emit_col(out, B, b, n1 + 2, a1.z, inv, b_poi, b_hour, b_wd);
        emit_col(out, B, b, n1 + 3, a1.w, inv, b_poi, b_hour, b_wd);
    }
}

// ---------------------------------------------------------------------------
// Launch
// ---------------------------------------------------------------------------
extern "C" void kernel_launch(void* const* d_in, const int* in_sizes, int n_in,
                              void* d_out, int out_size) {
    const int*   x        = (const int*)  d_in[0];
    const int*   lens     = (const int*)  d_in[1];
    const float* emb_poi  = (const float*)d_in[2];
    const float* emb_hour = (const float*)d_in[3];
    const float* emb_wd   = (const float*)d_in[4];
    const float* W_poi    = (const float*)d_in[5];
    const float* b_poi    = (const float*)d_in[6];
    const float* W_hour   = (const float*)d_in[7];
    const float* b_hour   = (const float*)d_in[8];
    const float* W_wd     = (const float*)d_in[9];
    const float* b_wd     = (const float*)d_in[10];

    const int B = in_sizes[0] / (L_WIN * 3);

    dim3 g1(TLSTRIDE / 32, (NROWS + 7) / 8);   // 33 x 146 tiles
    build_tl_kernel<<<g1, dim3(32, 8)>>>(emb_poi, emb_hour, emb_wd,
                                         W_poi, W_hour, W_wd);

    cbow_gather_kernel<<<B, 256>>>(x, lens, b_poi, b_hour, b_wd,
                                   (float*)d_out, B);
}

// round 3
// speedup vs baseline: 1.7456x; 1.7456x over previous
#include <cuda_runtime.h>

// Problem constants (fixed by the dataset)
#define L_WIN   10
#define D_EMB   100
#define V_POI   1000
#define V_HOUR  24
#define V_WD    7
#define N_HW    (V_HOUR * V_WD)           // 168 hour*weekday combo rows
#define NROWS   (V_POI + N_HW)            // 1168 token rows (poi | hw-combo)
#define TLSTRIDE 1024                     // main table cols = poi(1000)+hour(24)

// Main token-logit table (poi + hour logit columns):
//  rows [0,1000):    TL[p, n]          = emb_poi[p]  . W(n)[0:100]
//  rows [1000,1168): TL[1000+h*7+w, n] = emb_hour[h] . W(n)[100:200]
//                                       + emb_wd[w]  . W(n)[200:300]
//  cols [0,1000) = poi logits, [1000,1024) = hour logits.
__device__ __align__(128) float g_TL[NROWS * TLSTRIDE];   // 4.78 MB

// Compact weekday-logit table: cols [0,7) = weekday logits, col 7 = 0 pad.
__device__ __align__(128) float g_TLwd[NROWS * 8];        // 37 KB

// ---------------------------------------------------------------------------
// Weight fetch for "virtual column" n (0..1031) at depth (so + d) of the
// 300-wide concatenated classifier row.  n>=1031 -> 0 (pad).
// ---------------------------------------------------------------------------
__device__ __forceinline__ float wload(const float* __restrict__ W_poi,
                                       const float* __restrict__ W_hour,
                                       const float* __restrict__ W_wd,
                                       int n, int so, int d) {
    if (n < V_POI)          return W_poi[n * 300 + so + d];
    if (n < V_POI + V_HOUR) return W_hour[(n - V_POI) * 300 + so + d];
    if (n < 1031)           return W_wd[(n - 1024) * 300 + so + d];
    return 0.f;
}

__device__ __forceinline__ void store_tl(int r, int n, float v) {
    if (n < TLSTRIDE)       g_TL[r * TLSTRIDE + n] = v;
    else if (n < 1032)      g_TLwd[r * 8 + (n - 1024)] = v;
}

// ---------------------------------------------------------------------------
// Build kernel A: poi rows (r in [0,1000)), K=100 contraction.
// Tile: 16 rows x 64 cols, block 32x8, each thread computes 2x2 outputs.
// Wst is stored transposed [d][c] with stride 65 -> conflict-free LDS.
// ---------------------------------------------------------------------------
__global__ void build_poi_kernel(const float* __restrict__ emb_poi,
                                 const float* __restrict__ W_poi,
                                 const float* __restrict__ W_hour,
                                 const float* __restrict__ W_wd) {
    __shared__ float Wst[100][65];
    __shared__ float Es[16][100];

    const int n0  = blockIdx.x * 64;
    const int r0  = blockIdx.y * 16;
    const int tid = threadIdx.y * 32 + threadIdx.x;   // 256

    for (int idx = tid; idx < 64 * 100; idx += 256) {
        int c = idx / 100, d = idx - c * 100;
        Wst[d][c] = wload(W_poi, W_hour, W_wd, n0 + c, 0, d);
    }
    for (int idx = tid; idx < 16 * 100; idx += 256) {
        int i = idx / 100, d = idx - i * 100;
        int r = r0 + i;
        Es[i][d] = (r < V_POI) ? emb_poi[r * D_EMB + d] : 0.f;
    }
    __syncthreads();

    const int j  = threadIdx.x;
    const int i0 = threadIdx.y;
    const int i1 = threadIdx.y + 8;

    float a00 = 0.f, a01 = 0.f, a10 = 0.f, a11 = 0.f;
#pragma unroll 10
    for (int d = 0; d < 100; d++) {
        float w0 = Wst[d][j], w1 = Wst[d][j + 32];
        float e0 = Es[i0][d], e1 = Es[i1][d];
        a00 += e0 * w0; a01 += e0 * w1;
        a10 += e1 * w0; a11 += e1 * w1;
    }

    const int rA = r0 + i0, rB = r0 + i1;
    const int nA = n0 + j,  nB = n0 + j + 32;
    if (rA < V_POI) {
        if (nA < 1032) store_tl(rA, nA, a00);
        if (nB < 1032) store_tl(rA, nB, a01);
    }
    if (rB < V_POI) {
        if (nA < 1032) store_tl(rB, nA, a10);
        if (nB < 1032) store_tl(rB, nB, a11);
    }
}

// ---------------------------------------------------------------------------
// Build kernel B: hour*weekday combo rows (168), K=200 in two 100-passes.
// ---------------------------------------------------------------------------
__global__ void build_hw_kernel(const float* __restrict__ emb_hour,
                                const float* __restrict__ emb_wd,
                                const float* __restrict__ W_poi,
                                const float* __restrict__ W_hour,
                                const float* __restrict__ W_wd) {
    __shared__ float Wst[100][65];
    __shared__ float Es[16][100];

    const int n0  = blockIdx.x * 64;
    const int r0  = blockIdx.y * 16;   // combo index base
    const int tid = threadIdx.y * 32 + threadIdx.x;

    const int j  = threadIdx.x;
    const int i0 = threadIdx.y;
    const int i1 = threadIdx.y + 8;

    float a00 = 0.f, a01 = 0.f, a10 = 0.f, a11 = 0.f;

    for (int seg = 0; seg < 2; seg++) {
        const int so = 100 + seg * 100;
        for (int idx = tid; idx < 64 * 100; idx += 256) {
            int c = idx / 100, d = idx - c * 100;
            Wst[d][c] = wload(W_poi, W_hour, W_wd, n0 + c, so, d);
        }
        for (int idx = tid; idx < 16 * 100; idx += 256) {
            int i = idx / 100, d = idx - i * 100;
            int cc = r0 + i;
            float v = 0.f;
            if (cc < N_HW) {
                int h = cc / V_WD, w = cc - h * V_WD;
                v = (seg == 0) ? emb_hour[h * D_EMB + d] : emb_wd[w * D_EMB + d];
            }
            Es[i][d] = v;
        }
        __syncthreads();

#pragma unroll 10
        for (int d = 0; d < 100; d++) {
            float w0 = Wst[d][j], w1 = Wst[d][j + 32];
            float e0 = Es[i0][d], e1 = Es[i1][d];
            a00 += e0 * w0; a01 += e0 * w1;
            a10 += e1 * w0; a11 += e1 * w1;
        }
        __syncthreads();
    }

    const int cA = r0 + i0, cB = r0 + i1;
    const int nA = n0 + j,  nB = n0 + j + 32;
    if (cA < N_HW) {
        if (nA < 1032) store_tl(V_POI + cA, nA, a00);
        if (nB < 1032) store_tl(V_POI + cA, nB, a01);
    }
    if (cB < N_HW) {
        if (nA < 1032) store_tl(V_POI + cB, nA, a10);
        if (nB < 1032) store_tl(V_POI + cB, nB, a11);
    }
}

// ---------------------------------------------------------------------------
// Main gather: 2 samples per block, 256 threads, each thread owns 4 cols
// (float4).  2 independent row streams -> 2x MLP.
// ---------------------------------------------------------------------------
__global__ void __launch_bounds__(256, 8)
cbow_gather_kernel(const int* __restrict__ x,
                   const int* __restrict__ lens,
                   const float* __restrict__ b_poi,
                   const float* __restrict__ b_hour,
                   float* __restrict__ out,
                   int B) {
    __shared__ int   s_off[2][2 * L_WIN];   // row offsets in float4 units
    __shared__ int   s_T[2];
    __shared__ float s_inv[2];

    const int b0  = blockIdx.x * 2;
    const int tid = threadIdx.x;

    if (tid < 40) {
        int s = tid / 20, k = tid - s * 20;
        int l = k >> 1;
        const int* xp = x + ((b0 + s) * L_WIN + l) * 3;
        int row = ((k & 1) == 0) ? xp[0]
                                 : (V_POI + xp[1] * V_WD + xp[2]);
        s_off[s][k] = row * (TLSTRIDE / 4);
    }
    if (tid < 2) {
        int e = min(max(lens[b0 + tid], 1), L_WIN);
        s_T[tid]   = 2 * e;
        s_inv[tid] = 1.0f / (float)e;
    }
    __syncthreads();

    const int T0 = s_T[0], T1 = s_T[1];
    const int Tc = min(T0, T1);

    float4 acc0 = make_float4(0.f, 0.f, 0.f, 0.f);
    float4 acc1 = make_float4(0.f, 0.f, 0.f, 0.f);
    const float4* __restrict__ TL4 = reinterpret_cast<const float4*>(g_TL);

    int t = 0;
#pragma unroll 4
    for (; t < Tc; t++) {
        float4 v0 = TL4[s_off[0][t] + tid];
        float4 v1 = TL4[s_off[1][t] + tid];
        acc0.x += v0.x; acc0.y += v0.y; acc0.z += v0.z; acc0.w += v0.w;
        acc1.x += v1.x; acc1.y += v1.y; acc1.z += v1.z; acc1.w += v1.w;
    }
    for (; t < T0; t++) {
        float4 v0 = TL4[s_off[0][t] + tid];
        acc0.x += v0.x; acc0.y += v0.y; acc0.z += v0.z; acc0.w += v0.w;
    }
    for (int u = Tc; u < T1; u++) {
        float4 v1 = TL4[s_off[1][u] + tid];
        acc1.x += v1.x; acc1.y += v1.y; acc1.z += v1.z; acc1.w += v1.w;
    }

    const float i0 = s_inv[0], i1 = s_inv[1];
    float4* __restrict__ out4 = reinterpret_cast<float4*>(out);

    if (tid < 250) {                       // poi logits: cols 4*tid .. +3
        float4 bias = reinterpret_cast<const float4*>(b_poi)[tid];
        float4 r0, r1;
        r0.x = acc0.x * i0 + bias.x; r0.y = acc0.y * i0 + bias.y;
        r0.z = acc0.z * i0 + bias.z; r0.w = acc0.w * i0 + bias.w;
        r1.x = acc1.x * i1 + bias.x; r1.y = acc1.y * i1 + bias.y;
        r1.z = acc1.z * i1 + bias.z; r1.w = acc1.w * i1 + bias.w;
        out4[(size_t)b0 * 250 + tid]       = r0;   // out_poi[b0]
        out4[(size_t)(b0 + 1) * 250 + tid] = r1;   // out_poi[b0+1]
    } else {                               // hour logits: 24 cols = 6 float4
        int k = tid - 250;                 // 0..5
        float4 bias = reinterpret_cast<const float4*>(b_hour)[k];
        float4 r0, r1;
        r0.x = acc0.x * i0 + bias.x; r0.y = acc0.y * i0 + bias.y;
        r0.z = acc0.z * i0 + bias.z; r0.w = acc0.w * i0 + bias.w;
        r1.x = acc1.x * i1 + bias.x; r1.y = acc1.y * i1 + bias.y;
        r1.z = acc1.z * i1 + bias.z; r1.w = acc1.w * i1 + bias.w;
        float4* oh = reinterpret_cast<float4*>(out + (size_t)B * V_POI);
        oh[(size_t)b0 * 6 + k]       = r0;
        oh[(size_t)(b0 + 1) * 6 + k] = r1;
    }
}

// ---------------------------------------------------------------------------
// Weekday head: 8 threads per sample over the compact TLwd table.
// ---------------------------------------------------------------------------
__global__ void wd_kernel(const int* __restrict__ x,
                          const int* __restrict__ lens,
                          const float* __restrict__ b_wd,
                          float* __restrict__ out,
                          int B) {
    const int g = blockIdx.x * 32 + (threadIdx.x >> 3);   // sample
    const int k = threadIdx.x & 7;                        // col
    if (g >= B) return;

    int e = min(max(lens[g], 1), L_WIN);
    const int* xp = x + g * (L_WIN * 3);

    float acc = 0.f;
    for (int t = 0; t < e; t++) {
        int p = xp[t * 3 + 0];
        int h = xp[t * 3 + 1];
        int w = xp[t * 3 + 2];
        acc += g_TLwd[p * 8 + k];
        acc += g_TLwd[(V_POI + h * V_WD + w) * 8 + k];
    }
    if (k < V_WD)
        out[(size_t)B * (V_POI + V_HOUR) + (size_t)g * V_WD + k] =
            acc / (float)e + b_wd[k];
}

// ---------------------------------------------------------------------------
// Launch
// ---------------------------------------------------------------------------
extern "C" void kernel_launch(void* const* d_in, const int* in_sizes, int n_in,
                              void* d_out, int out_size) {
    const int*   x        = (const int*)  d_in[0];
    const int*   lens     = (const int*)  d_in[1];
    const float* emb_poi  = (const float*)d_in[2];
    const float* emb_hour = (const float*)d_in[3];
    const float* emb_wd   = (const float*)d_in[4];
    const float* W_poi    = (const float*)d_in[5];
    const float* b_poi    = (const float*)d_in[6];
    const float* W_hour   = (const float*)d_in[7];
    const float* b_hour   = (const float*)d_in[8];
    const float* W_wd     = (const float*)d_in[9];
    const float* b_wd     = (const float*)d_in[10];

    const int B = in_sizes[0] / (L_WIN * 3);

    // 1032 virtual cols -> 17 col tiles of 64
    build_poi_kernel<<<dim3(17, (V_POI + 15) / 16), dim3(32, 8)>>>(
        emb_poi, W_poi, W_hour, W_wd);
    build_hw_kernel<<<dim3(17, (N_HW + 15) / 16), dim3(32, 8)>>>(
        emb_hour, emb_wd, W_poi, W_hour, W_wd);

    cbow_gather_kernel<<<B / 2, 256>>>(x, lens, b_poi, b_hour,
                                       (float*)d_out, B);
    wd_kernel<<<(B + 31) / 32, 256>>>(x, lens, b_wd, (float*)d_out, B);
}

// round 5
// speedup vs baseline: 1.9876x; 1.1386x over previous
#include <cuda_runtime.h>
#include <cuda_fp16.h>

// Problem constants (fixed by the dataset)
#define L_WIN   10
#define D_EMB   100
#define V_POI   1000
#define V_HOUR  24
#define V_WD    7
#define N_HW    (V_HOUR * V_WD)           // 168 hour*weekday combo rows
#define NROWS   (V_POI + N_HW)            // 1168 token rows (poi | hw-combo)
#define TLCOLS  1024                      // main table cols = poi(1000)+hour(24)

// Main token-logit table in fp16 (accumulation happens in fp32):
//  rows [0,1000):    TL[p, n]          = emb_poi[p]  . W(n)[0:100]
//  rows [1000,1168): TL[1000+h*7+w, n] = emb_hour[h] . W(n)[100:200]
//                                       + emb_wd[w]  . W(n)[200:300]
//  cols [0,1000) = poi logits, [1000,1024) = hour logits.
__device__ __align__(128) __half g_TLh[NROWS * TLCOLS];   // 2.39 MB

// Compact weekday-logit table (fp32): cols [0,7) weekday logits, col 7 pad.
__device__ __align__(128) float g_TLwd[NROWS * 8];        // 37 KB

// ---------------------------------------------------------------------------
// Weight fetch for "virtual column" n (0..1031) at depth (so + d) of the
// 300-wide concatenated classifier row.  n>=1031 -> 0 (pad).
// ---------------------------------------------------------------------------
__device__ __forceinline__ float wload(const float* __restrict__ W_poi,
                                       const float* __restrict__ W_hour,
                                       const float* __restrict__ W_wd,
                                       int n, int so, int d) {
    if (n < V_POI)          return W_poi[n * 300 + so + d];
    if (n < V_POI + V_HOUR) return W_hour[(n - V_POI) * 300 + so + d];
    if (n < 1031)           return W_wd[(n - 1024) * 300 + so + d];
    return 0.f;
}

__device__ __forceinline__ void store_tl(int r, int n, float v) {
    if (n < TLCOLS)         g_TLh[r * TLCOLS + n] = __float2half_rn(v);
    else if (n < 1032)      g_TLwd[r * 8 + (n - 1024)] = v;
}

// ---------------------------------------------------------------------------
// Build kernel A: poi rows (r in [0,1000)), K=100 contraction.
// Tile: 16 rows x 64 cols, block 32x8, each thread computes 2x2 outputs.
// ---------------------------------------------------------------------------
__global__ void build_poi_kernel(const float* __restrict__ emb_poi,
                                 const float* __restrict__ W_poi,
                                 const float* __restrict__ W_hour,
                                 const float* __restrict__ W_wd) {
    __shared__ float Wst[100][65];
    __shared__ float Es[16][100];

    const int n0  = blockIdx.x * 64;
    const int r0  = blockIdx.y * 16;
    const int tid = threadIdx.y * 32 + threadIdx.x;   // 256

    for (int idx = tid; idx < 64 * 100; idx += 256) {
        int c = idx / 100, d = idx - c * 100;
        Wst[d][c] = wload(W_poi, W_hour, W_wd, n0 + c, 0, d);
    }
    for (int idx = tid; idx < 16 * 100; idx += 256) {
        int i = idx / 100, d = idx - i * 100;
        int r = r0 + i;
        Es[i][d] = (r < V_POI) ? emb_poi[r * D_EMB + d] : 0.f;
    }
    __syncthreads();

    const int j  = threadIdx.x;
    const int i0 = threadIdx.y;
    const int i1 = threadIdx.y + 8;

    float a00 = 0.f, a01 = 0.f, a10 = 0.f, a11 = 0.f;
#pragma unroll 10
    for (int d = 0; d < 100; d++) {
        float w0 = Wst[d][j], w1 = Wst[d][j + 32];
        float e0 = Es[i0][d], e1 = Es[i1][d];
        a00 += e0 * w0; a01 += e0 * w1;
        a10 += e1 * w0; a11 += e1 * w1;
    }

    const int rA = r0 + i0, rB = r0 + i1;
    const int nA = n0 + j,  nB = n0 + j + 32;
    if (rA < V_POI) {
        if (nA < 1032) store_tl(rA, nA, a00);
        if (nB < 1032) store_tl(rA, nB, a01);
    }
    if (rB < V_POI) {
        if (nA < 1032) store_tl(rB, nA, a10);
        if (nB < 1032) store_tl(rB, nB, a11);
    }
}

// ---------------------------------------------------------------------------
// Build kernel B: hour*weekday combo rows (168), K=200 in two 100-passes.
// ---------------------------------------------------------------------------
__global__ void build_hw_kernel(const float* __restrict__ emb_hour,
                                const float* __restrict__ emb_wd,
                                const float* __restrict__ W_poi,
                                const float* __restrict__ W_hour,
                                const float* __restrict__ W_wd) {
    __shared__ float Wst[100][65];
    __shared__ float Es[16][100];

    const int n0  = blockIdx.x * 64;
    const int r0  = blockIdx.y * 16;   // combo index base
    const int tid = threadIdx.y * 32 + threadIdx.x;

    const int j  = threadIdx.x;
    const int i0 = threadIdx.y;
    const int i1 = threadIdx.y + 8;

    float a00 = 0.f, a01 = 0.f, a10 = 0.f, a11 = 0.f;

    for (int seg = 0; seg < 2; seg++) {
        const int so = 100 + seg * 100;
        for (int idx = tid; idx < 64 * 100; idx += 256) {
            int c = idx / 100, d = idx - c * 100;
            Wst[d][c] = wload(W_poi, W_hour, W_wd, n0 + c, so, d);
        }
        for (int idx = tid; idx < 16 * 100; idx += 256) {
            int i = idx / 100, d = idx - i * 100;
            int cc = r0 + i;
            float v = 0.f;
            if (cc < N_HW) {
                int h = cc / V_WD, w = cc - h * V_WD;
                v = (seg == 0) ? emb_hour[h * D_EMB + d] : emb_wd[w * D_EMB + d];
            }
            Es[i][d] = v;
        }
        __syncthreads();

#pragma unroll 10
        for (int d = 0; d < 100; d++) {
            float w0 = Wst[d][j], w1 = Wst[d][j + 32];
            float e0 = Es[i0][d], e1 = Es[i1][d];
            a00 += e0 * w0; a01 += e0 * w1;
            a10 += e1 * w0; a11 += e1 * w1;
        }
        __syncthreads();
    }

    const int cA = r0 + i0, cB = r0 + i1;
    const int nA = n0 + j,  nB = n0 + j + 32;
    if (cA < N_HW) {
        if (nA < 1032) store_tl(V_POI + cA, nA, a00);
        if (nB < 1032) store_tl(V_POI + cA, nB, a01);
    }
    if (cB < N_HW) {
        if (nA < 1032) store_tl(V_POI + cB, nA, a10);
        if (nB < 1032) store_tl(V_POI + cB, nB, a11);
    }
}

// ---------------------------------------------------------------------------
// Main gather: 2 samples per block (two 128-thread groups = 4 warps each).
// Each lane owns 8 columns = one 16B load (8 fp16) per table row.
// Accumulation in fp32.  Row offsets hoisted to registers: loop body is
// pure LDG.128 + CVT + FADD.
// ---------------------------------------------------------------------------
__global__ void __launch_bounds__(256, 8)
cbow_gather_kernel(const int* __restrict__ x,
                   const int* __restrict__ lens,
                   const float* __restrict__ b_poi,
                   const float* __restrict__ b_hour,
                   float* __restrict__ out,
                   int B) {
    __shared__ int   s_off[2][2 * L_WIN];   // row offsets in uint4 (16B) units
    __shared__ int   s_T[2];
    __shared__ float s_inv[2];

    const int b0  = blockIdx.x * 2;
    const int tid = threadIdx.x;

    if (tid < 40) {
        int s = tid / 20, k = tid - s * 20;
        int l = k >> 1;
        const int* xp = x + ((b0 + s) * L_WIN + l) * 3;
        int row = ((k & 1) == 0) ? xp[0]
                                 : (V_POI + xp[1] * V_WD + xp[2]);
        s_off[s][k] = row * (TLCOLS * 2 / 16);   // row * 128
    }
    if (tid < 2) {
        int e = min(max(lens[b0 + tid], 1), L_WIN);
        s_T[tid]   = 2 * e;
        s_inv[tid] = 1.0f / (float)e;
    }
    __syncthreads();

    const int g    = tid >> 7;     // sample group 0/1 (warp-aligned)
    const int lane = tid & 127;    // column group: 8 cols each

    const int   T   = s_T[g];
    const float inv = s_inv[g];
    const int*  off = s_off[g];

    float acc[8];
#pragma unroll
    for (int i = 0; i < 8; i++) acc[i] = 0.f;

    const uint4* __restrict__ TLv = reinterpret_cast<const uint4*>(g_TLh) + lane;

    // Process rows in batches of 4: all offsets read first, then 4 LDG.128
    // issued back-to-back (MLP=4), then the converts/adds.
    int t = 0;
    for (; t + 4 <= T; t += 4) {
        int o0 = off[t], o1 = off[t + 1], o2 = off[t + 2], o3 = off[t + 3];
        uint4 v0 = TLv[o0];
        uint4 v1 = TLv[o1];
        uint4 v2 = TLv[o2];
        uint4 v3 = TLv[o3];
#pragma unroll
        for (int q = 0; q < 4; q++) {
            uint4 v = (q == 0) ? v0 : (q == 1) ? v1 : (q == 2) ? v2 : v3;
            float2 f0 = __half22float2(*reinterpret_cast<const __half2*>(&v.x));
            float2 f1 = __half22float2(*reinterpret_cast<const __half2*>(&v.y));
            float2 f2 = __half22float2(*reinterpret_cast<const __half2*>(&v.z));
            float2 f3 = __half22float2(*reinterpret_cast<const __half2*>(&v.w));
            acc[0] += f0.x; acc[1] += f0.y;
            acc[2] += f1.x; acc[3] += f1.y;
            acc[4] += f2.x; acc[5] += f2.y;
            acc[6] += f3.x; acc[7] += f3.y;
        }
    }
    for (; t < T; t++) {
        uint4 v = TLv[off[t]];
        float2 f0 = __half22float2(*reinterpret_cast<const __half2*>(&v.x));
        float2 f1 = __half22float2(*reinterpret_cast<const __half2*>(&v.y));
        float2 f2 = __half22float2(*reinterpret_cast<const __half2*>(&v.z));
        float2 f3 = __half22float2(*reinterpret_cast<const __half2*>(&v.w));
        acc[0] += f0.x; acc[1] += f0.y;
        acc[2] += f1.x; acc[3] += f1.y;
        acc[4] += f2.x; acc[5] += f2.y;
        acc[6] += f3.x; acc[7] += f3.y;
    }

    const int b = b0 + g;
    if (lane < 125) {                      // poi logits: cols lane*8 .. +7
        const float4* bp = reinterpret_cast<const float4*>(b_poi) + lane * 2;
        float4 bv0 = bp[0], bv1 = bp[1];
        float4 o0, o1;
        o0.x = acc[0] * inv + bv0.x; o0.y = acc[1] * inv + bv0.y;
        o0.z = acc[2] * inv + bv0.z; o0.w = acc[3] * inv + bv0.w;
        o1.x = acc[4] * inv + bv1.x; o1.y = acc[5] * inv + bv1.y;
        o1.z = acc[6] * inv + bv1.z; o1.w = acc[7] * inv + bv1.w;
        float4* dst = reinterpret_cast<float4*>(out + (size_t)b * V_POI) + lane * 2;
        dst[0] = o0; dst[1] = o1;
    } else {                               // hour logits: cols 1000..1023
        int k = lane - 125;                // 0..2 -> 8 cols each
        const float4* bh = reinterpret_cast<const float4*>(b_hour) + k * 2;
        float4 bv0 = bh[0], bv1 = bh[1];
        float4 o0, o1;
        o0.x = acc[0] * inv + bv0.x; o0.y = acc[1] * inv + bv0.y;
        o0.z = acc[2] * inv + bv0.z; o0.w = acc[3] * inv + bv0.w;
        o1.x = acc[4] * inv + bv1.x; o1.y = acc[5] * inv + bv1.y;
        o1.z = acc[6] * inv + bv1.z; o1.w = acc[7] * inv + bv1.w;
        float4* dst = reinterpret_cast<float4*>(
            out + (size_t)B * V_POI + (size_t)b * V_HOUR) + k * 2;
        dst[0] = o0; dst[1] = o1;
    }
}

// ---------------------------------------------------------------------------
// Weekday head: 8 threads per sample over the compact fp32 TLwd table.
// ---------------------------------------------------------------------------
__global__ void wd_kernel(const int* __restrict__ x,
                          const int* __restrict__ lens,
                          const float* __restrict__ b_wd,
                          float* __restrict__ out,
                          int B) {
    const int g = blockIdx.x * 32 + (threadIdx.x >> 3);   // sample
    const int k = threadIdx.x & 7;                        // col
    if (g >= B) return;

    int e = min(max(lens[g], 1), L_WIN);
    const int* xp = x + g * (L_WIN * 3);

    float acc = 0.f;
    for (int t = 0; t < e; t++) {
        int p = xp[t * 3 + 0];
        int h = xp[t * 3 + 1];
        int w = xp[t * 3 + 2];
        acc += g_TLwd[p * 8 + k];
        acc += g_TLwd[(V_POI + h * V_WD + w) * 8 + k];
    }
    if (k < V_WD)
        out[(size_t)B * (V_POI + V_HOUR) + (size_t)g * V_WD + k] =
            acc / (float)e + b_wd[k];
}

// ---------------------------------------------------------------------------
// Launch
// ---------------------------------------------------------------------------
extern "C" void kernel_launch(void* const* d_in, const int* in_sizes, int n_in,
                              void* d_out, int out_size) {
    const int*   x        = (const int*)  d_in[0];
    const int*   lens     = (const int*)  d_in[1];
    const float* emb_poi  = (const float*)d_in[2];
    const float* emb_hour = (const float*)d_in[3];
    const float* emb_wd   = (const float*)d_in[4];
    const float* W_poi    = (const float*)d_in[5];
    const float* b_poi    = (const float*)d_in[6];
    const float* W_hour   = (const float*)d_in[7];
    const float* b_hour   = (const float*)d_in[8];
    const float* W_wd     = (const float*)d_in[9];
    const float* b_wd     = (const float*)d_in[10];

    const int B = in_sizes[0] / (L_WIN * 3);

    // 1032 virtual cols -> 17 col tiles of 64
    build_poi_kernel<<<dim3(17, (V_POI + 15) / 16), dim3(32, 8)>>>(
        emb_poi, W_poi, W_hour, W_wd);
    build_hw_kernel<<<dim3(17, (N_HW + 15) / 16), dim3(32, 8)>>>(
        emb_hour, emb_wd, W_poi, W_hour, W_wd);

    cbow_gather_kernel<<<B / 2, 256>>>(x, lens, b_poi, b_hour,
                                       (float*)d_out, B);
    wd_kernel<<<(B + 31) / 32, 256>>>(x, lens, b_wd, (float*)d_out, B);
}